// round 8
// baseline (speedup 1.0000x reference)
#include <cuda_runtime.h>
#include <cstdint>

// GraphConv: out[row[e], :] += edge_vals[e] * x[col[e], :]   (D_FEAT = 64)
//
// R7 (= R5 resubmit, infra flake): 2D-sliced passes (2 row-slices x 2
// col-slices, serpentine order) so the active out-slice (64 MB) and active
// x-slice (64 MB) are simultaneously ~L2-resident, plus 4x edge unroll per
// half-warp to raise gather MLP (R4 measured latency-bound passes: DRAM
// 40.8%, issue 37.9%, nothing saturated). Index loads are front-batched
// before predication so ptxas can issue them as one MLP group.

#define D_FEAT 64
#define D_VEC4 16
#define UNROLL 4

__global__ void __launch_bounds__(256) spmm_tile_kernel(
    const float4* __restrict__ x4,       // [N_NODES * 16] float4
    const float*  __restrict__ edge_vals,
    const int*    __restrict__ row,
    const int*    __restrict__ col,
    float*        __restrict__ out,      // [N_NODES * 64] floats
    int n_edges, int rlo, int rhi, int clo, int chi)
{
    const int lane16 = threadIdx.x & 15;
    const long long gtid = (long long)blockIdx.x * blockDim.x + threadIdx.x;
    const long long n_hw = ((long long)gridDim.x * blockDim.x) >> 4;
    const long long hw   = gtid >> 4;

    // Bulk region: all UNROLL lanes in-bounds (no per-edge bounds check).
    const long long bulk = (long long)(n_edges / UNROLL) * UNROLL;

    long long base = hw * UNROLL;
    const long long stride = n_hw * UNROLL;

    for (; base + UNROLL <= bulk + ((base < bulk) ? 0 : 0) && base + UNROLL <= n_edges + UNROLL; base += stride) {
        if (base >= n_edges) break;
        const bool full = (base + UNROLL <= n_edges);

        int rr[UNROLL], cc[UNROLL];
        if (full) {
            // Front-batch all 8 index loads -> one MLP group.
#pragma unroll
            for (int j = 0; j < UNROLL; ++j) rr[j] = __ldg(row + base + j);
#pragma unroll
            for (int j = 0; j < UNROLL; ++j) cc[j] = __ldg(col + base + j);
        } else {
#pragma unroll
            for (int j = 0; j < UNROLL; ++j) {
                long long e = base + j;
                rr[j] = (e < n_edges) ? __ldg(row + e) : -1;
                cc[j] = (e < n_edges) ? __ldg(col + e) : -1;
            }
        }

        bool act[UNROLL];
        float v[UNROLL];
        float4 xv[UNROLL];
#pragma unroll
        for (int j = 0; j < UNROLL; ++j) {
            act[j] = (rr[j] >= rlo) & (rr[j] < rhi) & (cc[j] >= clo) & (cc[j] < chi);
            if (act[j]) {
                v[j]  = __ldg(edge_vals + base + j);
                xv[j] = __ldg(x4 + (long long)cc[j] * D_VEC4 + lane16);
            }
        }

#pragma unroll
        for (int j = 0; j < UNROLL; ++j) {
            if (act[j]) {
                float4 m;
                m.x = xv[j].x * v[j];
                m.y = xv[j].y * v[j];
                m.z = xv[j].z * v[j];
                m.w = xv[j].w * v[j];
                float* dst = out + (long long)rr[j] * D_FEAT + lane16 * 4;
                asm volatile(
                    "red.global.add.v4.f32 [%0], {%1, %2, %3, %4};"
                    :: "l"(dst), "f"(m.x), "f"(m.y), "f"(m.z), "f"(m.w)
                    : "memory");
            }
        }
    }
}

extern "C" void kernel_launch(void* const* d_in, const int* in_sizes, int n_in,
                              void* d_out, int out_size)
{
    const float* x         = (const float*)d_in[0];
    const float* edge_vals = (const float*)d_in[1];
    const int*   row       = (const int*)d_in[2];
    const int*   col       = (const int*)d_in[3];
    float*       out       = (float*)d_out;

    const int n_edges = in_sizes[1];
    const int n_nodes = in_sizes[0] / D_FEAT;

    // Output is poisoned; zero it first (memset node is graph-capturable).
    cudaMemsetAsync(out, 0, (size_t)out_size * sizeof(float));

    const int threads = 256;
    const int blocks  = 1184;   // 148 SMs x 8 CTAs

    const int rhalf = (n_nodes + 1) / 2;
    const int chalf = (n_nodes + 1) / 2;

    // Serpentine order: consecutive passes share either the out-slice or the
    // x-slice in L2: (r0,c0) -> (r0,c1) -> (r1,c1) -> (r1,c0).
    const int order[4][2] = { {0,0}, {0,1}, {1,1}, {1,0} };

    for (int p = 0; p < 4; ++p) {
        int ri = order[p][0], ci = order[p][1];
        int rlo = ri * rhalf, rhi = (ri == 0) ? rhalf : n_nodes;
        int clo = ci * chalf, chi = (ci == 0) ? chalf : n_nodes;
        spmm_tile_kernel<<<blocks, threads>>>(
            (const float4*)x, edge_vals, row, col, out,
            n_edges, rlo, rhi, clo, chi);
    }
}

// round 14
// speedup vs baseline: 1.6485x; 1.6485x over previous
#include <cuda_runtime.h>
#include <cstdint>

// GraphConv: out[row[e], :] += edge_vals[e] * x[col[e], :]   (D_FEAT = 64)
//
// R12: 2-pass row-sliced atomic scatter, no device-global scratch.
//  - R1 (single pass): 683us, DRAM 71.6%, ~3.76 GB traffic (output thrash).
//  - R4 (4 passes):    685us, per-pass latency-floor-bound (all pipes ~40%);
//    traffic fixed but 4x edge rescan ate the savings.
//  - R7 (unroll):      958us, register pressure killed occupancy.
// => 2 passes: out-slice 64 MB stays L2-resident (thrash gone), rescan waste
//    halved vs R4, body kept at 32 regs / 95% occupancy.

#define D_FEAT 64
#define D_VEC4 16

__global__ void __launch_bounds__(256) spmm_slice_kernel(
    const float4* __restrict__ x4,       // [N_NODES * 16] float4
    const float*  __restrict__ edge_vals,
    const int*    __restrict__ row,
    const int*    __restrict__ col,
    float*        __restrict__ out,      // [N_NODES * 64] floats
    int n_edges, int lo, int hi)
{
    const int lane16 = threadIdx.x & 15;
    const long long gtid = (long long)blockIdx.x * blockDim.x + threadIdx.x;
    const long long n_hw = ((long long)gridDim.x * blockDim.x) >> 4;

    for (long long e = gtid >> 4; e < n_edges; e += n_hw) {
        const int r = __ldg(row + e);              // broadcast within half-warp
        if (r < lo || r >= hi) continue;           // uniform per half-warp

        const int   c = __ldg(col + e);
        const float v = __ldg(edge_vals + e);

        float4 xv = __ldg(x4 + (long long)c * D_VEC4 + lane16);

        float4 m;
        m.x = xv.x * v;
        m.y = xv.y * v;
        m.z = xv.z * v;
        m.w = xv.w * v;

        float* dst = out + (long long)r * D_FEAT + lane16 * 4;
        asm volatile(
            "red.global.add.v4.f32 [%0], {%1, %2, %3, %4};"
            :: "l"(dst), "f"(m.x), "f"(m.y), "f"(m.z), "f"(m.w)
            : "memory");
    }
}

extern "C" void kernel_launch(void* const* d_in, const int* in_sizes, int n_in,
                              void* d_out, int out_size)
{
    const float* x         = (const float*)d_in[0];
    const float* edge_vals = (const float*)d_in[1];
    const int*   row       = (const int*)d_in[2];
    const int*   col       = (const int*)d_in[3];
    float*       out       = (float*)d_out;

    const int n_edges = in_sizes[1];
    const int n_nodes = in_sizes[0] / D_FEAT;

    // Output is poisoned; zero it first (memset node is graph-capturable).
    cudaMemsetAsync(out, 0, (size_t)out_size * sizeof(float));

    const int threads = 256;
    const int blocks  = 1184;   // 148 SMs x 8 CTAs of 256 = full occupancy

    // 2 passes: each out-slice is 64 MB -> L2-resident while being atomically
    // accumulated; pass boundary (stream order) gives each slice the L2.
    const int half = (n_nodes + 1) / 2;
    spmm_slice_kernel<<<blocks, threads>>>(
        (const float4*)x, edge_vals, row, col, out, n_edges, 0, half);
    spmm_slice_kernel<<<blocks, threads>>>(
        (const float4*)x, edge_vals, row, col, out, n_edges, half, n_nodes);
}

// round 16
// speedup vs baseline: 1.7766x; 1.0778x over previous
#include <cuda_runtime.h>
#include <cstdint>

// GraphConv: out[row[e], :] += edge_vals[e] * x[col[e], :]   (D_FEAT = 64)
//
// R13: 2-pass row-sliced atomic scatter (R12 WIN: 581us) with doubled MLP:
// 8 lanes per edge, each lane gathers TWO float4s and issues TWO red.v4.
// Per warp: 4 independent edge gathers (vs 2), per lane 2 LDGs in flight
// (vs 1), at ~constant register count (R7 showed unrolled arrays kill occ).
// Per-pass was DRAM 63.2% / issue 28.2% -> latency-exposed, not roofline.

#define D_FEAT 64
#define D_VEC4 16

__global__ void __launch_bounds__(256) spmm_slice_kernel(
    const float4* __restrict__ x4,       // [N_NODES * 16] float4
    const float*  __restrict__ edge_vals,
    const int*    __restrict__ row,
    const int*    __restrict__ col,
    float*        __restrict__ out,      // [N_NODES * 64] floats
    int n_edges, int lo, int hi)
{
    const int lane8 = threadIdx.x & 7;
    const long long gtid = (long long)blockIdx.x * blockDim.x + threadIdx.x;
    const long long n_sw = ((long long)gridDim.x * blockDim.x) >> 3;

    for (long long e = gtid >> 3; e < n_edges; e += n_sw) {
        const int r = __ldg(row + e);              // broadcast within 8 lanes
        if (r < lo || r >= hi) continue;           // uniform per 8-lane group

        const int   c = __ldg(col + e);
        const float v = __ldg(edge_vals + e);

        // Two independent gathers per lane: lines c*64B.. and +128B.
        const float4* src = x4 + (long long)c * D_VEC4 + lane8;
        float4 a = __ldg(src);
        float4 b = __ldg(src + 8);

        float4 ma, mb;
        ma.x = a.x * v; ma.y = a.y * v; ma.z = a.z * v; ma.w = a.w * v;
        mb.x = b.x * v; mb.y = b.y * v; mb.z = b.z * v; mb.w = b.w * v;

        float* dst = out + (long long)r * D_FEAT + lane8 * 4;
        asm volatile(
            "red.global.add.v4.f32 [%0], {%1, %2, %3, %4};"
            :: "l"(dst), "f"(ma.x), "f"(ma.y), "f"(ma.z), "f"(ma.w)
            : "memory");
        asm volatile(
            "red.global.add.v4.f32 [%0], {%1, %2, %3, %4};"
            :: "l"(dst + 32), "f"(mb.x), "f"(mb.y), "f"(mb.z), "f"(mb.w)
            : "memory");
    }
}

extern "C" void kernel_launch(void* const* d_in, const int* in_sizes, int n_in,
                              void* d_out, int out_size)
{
    const float* x         = (const float*)d_in[0];
    const float* edge_vals = (const float*)d_in[1];
    const int*   row       = (const int*)d_in[2];
    const int*   col       = (const int*)d_in[3];
    float*       out       = (float*)d_out;

    const int n_edges = in_sizes[1];
    const int n_nodes = in_sizes[0] / D_FEAT;

    // Output is poisoned; zero it first (memset node is graph-capturable).
    cudaMemsetAsync(out, 0, (size_t)out_size * sizeof(float));

    const int threads = 256;
    const int blocks  = 1184;   // 148 SMs x 8 CTAs of 256

    // 2 passes: each 64 MB out-slice stays L2-resident while accumulated.
    const int half = (n_nodes + 1) / 2;
    spmm_slice_kernel<<<blocks, threads>>>(
        (const float4*)x, edge_vals, row, col, out, n_edges, 0, half);
    spmm_slice_kernel<<<blocks, threads>>>(
        (const float4*)x, edge_vals, row, col, out, n_edges, half, n_nodes);
}